// round 14
// baseline (speedup 1.0000x reference)
#include <cuda_runtime.h>
#include <cuda_fp16.h>
#include <mma.h>
#include <math.h>
#include <cstdint>

using namespace nvcuda;

// Problem dims
static constexpr int Bn = 256, Sn = 20, En = 512, Hn = 512, Vn = 32000;
static constexpr int DIN1 = Sn * En + 2 * En;   // 11264
static constexpr int K1   = DIN1 + Hn;          // 11776 ([x | h0] concat)
static constexpr int NG   = 4 * Hn;             // 2048 gates

// Scratch (device globals; allocation is forbidden)
__device__ __align__(16) __half g_xh[Bn * K1];        // A of layer 1 (half)
__device__ __align__(16) __half g_hduph[Bn * 2 * Hn]; // [h|h] half (layers 2-4 A)
__device__ __align__(16) __half g_h4h[Bn * Hn];       // h4 half (decode A)
__device__ float g_part[8 * Bn * NG];                 // split-K partials
__device__ float g_c[Bn * Hn];

// ---------------------------------------------------------------------------
// Helpers
// ---------------------------------------------------------------------------
#define CP16(dst, src) \
    asm volatile("cp.async.cg.shared.global [%0], [%1], 16;\n" :: "r"(dst), "l"(src))

__device__ __forceinline__ void split4h(const float4 f, __half* hi, __half* lo) {
    float v[4] = {f.x, f.y, f.z, f.w};
#pragma unroll
    for (int i = 0; i < 4; i++) {
        __half h = __float2half_rn(v[i]);
        hi[i] = h;
        lo[i] = __float2half_rn(v[i] - __half2float(h));
    }
}

// ---------------------------------------------------------------------------
// build_x: concatenated input row as HALF: [enc | we | pe[spk] | h0]
// ---------------------------------------------------------------------------
__global__ void build_x(const float* __restrict__ enc, const float* __restrict__ we,
                        const float* __restrict__ h0, const int* __restrict__ spk,
                        const float* __restrict__ pe) {
    int idx = blockIdx.x * blockDim.x + threadIdx.x;
    if (idx >= Bn * K1) return;
    int b = idx / K1;
    int k = idx - b * K1;
    float v;
    if (k < Sn * En)            v = enc[b * Sn * En + k];
    else if (k < Sn * En + En)  v = we[b * En + (k - Sn * En)];
    else if (k < DIN1)          v = pe[spk[b] * En + (k - Sn * En - En)];
    else                        v = h0[b * Hn + (k - DIN1)];
    g_xh[idx] = __float2half_rn(v);
}

// ---------------------------------------------------------------------------
// fp16 GEMM, tall 256x64, BK=32 — SINGLE barrier per K-iter.
//   A: half in gmem -> 3-stage cp.async pipeline (no conversion).
//   B: f32 weights -> LDG to regs one chunk ahead -> reg split -> STS halves.
//   acc += a*bh; acc += a*bl  (fp32 accumulators, 2-MMA compensation).
// Iter it: STS_B(it)->BH[it&1] ; ldgB(it+1) ; wait_group ; __syncthreads ;
//          issueA(it+2) ; MMA(it).
// Races (all barrier-ordered):
//   STS_B(it) vs readers of BH[it&1]: last readers MMA(it-2); every warp
//     passes barrier(it-1) only after MMA(it-2). Safe.
//   issueA(it+2) writes stage (it-1)%3: readers MMA(it-1) complete before
//     any warp reaches barrier(it); issue is after barrier(it). Safe.
// grid = (N/64, 1, KS). 256 threads, 8 warps (4x2), warp tile 64x32.
// ---------------------------------------------------------------------------
static constexpr int ALD = 40;                  // halfs per A row (32+8 pad)
static constexpr int BLD = 72;                  // halfs per B half-plane row
static constexpr int A_STAGE = 256 * ALD * 2;   // 20480 B
static constexpr int BH_STAGE = 32 * BLD * 2;   // 4608 B
static constexpr int SA  = 0;                   // 3 stages
static constexpr int SBH = SA + 3 * A_STAGE;    // 2 buffers
static constexpr int SBL = SBH + 2 * BH_STAGE;  // 2 buffers
static constexpr int GEMM_SMEM = SBL + 2 * BH_STAGE;  // 79872 B

template <int DUAL>
__global__ __launch_bounds__(256, 2)
void gemm_cp(const __half* __restrict__ A, const float* __restrict__ B0,
             const float* __restrict__ B1, float* __restrict__ Cout,
             int N, int K, int Ksplit, int Kchunk) {
    extern __shared__ char smem[];
    uint32_t sb;
    asm("{ .reg .u64 t; cvta.to.shared.u64 t, %1; cvt.u32.u64 %0, t; }"
        : "=r"(sb) : "l"(smem));

    const int n0 = blockIdx.x * 64;
    const int ks = blockIdx.z;
    const int kbase = ks * Kchunk;
    const int iters = Kchunk / 32;   // >= 4 for every launch in this problem
    const int tid = threadIdx.x;

    // A loader (cp.async): 4 threads per 64B row, 4 passes of 64 rows
    const int a_row4 = tid >> 2;
    const int a_chk = tid & 3;
    // B loader (LDG f32): row tid>>3 (0..31), col (tid&7)*8 -> 2 float4
    const int b_row = tid >> 3;
    const int b_col = (tid & 7) * 8;

    const int wid = tid >> 5;
    const int wm = wid >> 1;   // 0..3 -> m offset wm*64
    const int wn = wid & 1;    // 0..1 -> n offset wn*32

    wmma::fragment<wmma::accumulator, 16, 16, 16, float> acc[4][2];
#pragma unroll
    for (int i = 0; i < 4; i++)
#pragma unroll
        for (int j = 0; j < 2; j++) wmma::fill_fragment(acc[i][j], 0.f);

    float4 bReg[2];

    auto issueA = [&](int chunk) {
        const int s = chunk % 3;
        const int k0 = kbase + chunk * 32;
        uint32_t sa = sb + SA + s * A_STAGE;
#pragma unroll
        for (int p = 0; p < 4; p++) {
            int row = a_row4 + p * 64;
            const __half* src = A + (size_t)row * K + k0 + a_chk * 8;
            CP16(sa + row * 80 + a_chk * 16, src);
        }
        asm volatile("cp.async.commit_group;\n");
    };

    auto ldgB = [&](int chunk) {
        int gk = kbase + chunk * 32 + b_row;
        const float* brow;
        if (DUAL && gk >= Ksplit)
            brow = B1 + (size_t)(gk - Ksplit) * N + n0 + b_col;
        else
            brow = B0 + (size_t)gk * N + n0 + b_col;
        bReg[0] = *(const float4*)(brow);
        bReg[1] = *(const float4*)(brow + 4);
    };

    auto stsB = [&](int chunk) {
        const int sd = chunk & 1;
        __half hq[4], lq[4];
        __half* bh = (__half*)(smem + SBH + sd * BH_STAGE) + b_row * BLD + b_col;
        __half* bl = (__half*)(smem + SBL + sd * BH_STAGE) + b_row * BLD + b_col;
#pragma unroll
        for (int j = 0; j < 2; j++) {
            split4h(bReg[j], hq, lq);
            *(uint2*)(bh + j * 4) = *(uint2*)hq;
            *(uint2*)(bl + j * 4) = *(uint2*)lq;
        }
    };

    // Prologue
    ldgB(0);
    issueA(0);
    issueA(1);

    for (int it = 0; it < iters; ++it) {
        const int s = it % 3;
        const int sd = it & 1;

        stsB(it);                       // BH/BL[it&1] — safe (see header)
        if (it + 1 < iters) ldgB(it + 1);   // B LDG in flight during MMA

        if (it == iters - 1)
            asm volatile("cp.async.wait_group 0;\n");
        else
            asm volatile("cp.async.wait_group 1;\n");
        __syncthreads();   // A chunk `it` + this iter's B halves visible

        if (it + 2 < iters) issueA(it + 2);

        const __half* ah = (const __half*)(smem + SA + s * A_STAGE) + (wm * 64) * ALD;
        const __half* bh = (const __half*)(smem + SBH + sd * BH_STAGE) + wn * 32;
        const __half* bl = (const __half*)(smem + SBL + sd * BH_STAGE) + wn * 32;

#pragma unroll
        for (int kk = 0; kk < 2; ++kk) {
            wmma::fragment<wmma::matrix_b, 16, 16, 16, __half, wmma::row_major> bfh[2],
                bfl[2];
#pragma unroll
            for (int j = 0; j < 2; j++) {
                wmma::load_matrix_sync(bfh[j], bh + kk * 16 * BLD + j * 16, BLD);
                wmma::load_matrix_sync(bfl[j], bl + kk * 16 * BLD + j * 16, BLD);
            }
#pragma unroll
            for (int i = 0; i < 4; i++) {
                wmma::fragment<wmma::matrix_a, 16, 16, 16, __half, wmma::row_major> af;
                wmma::load_matrix_sync(af, ah + i * 16 * ALD + kk * 16, ALD);
#pragma unroll
                for (int j = 0; j < 2; j++) {
                    wmma::mma_sync(acc[i][j], af, bfh[j], acc[i][j]);
                    wmma::mma_sync(acc[i][j], af, bfl[j], acc[i][j]);
                }
            }
        }
    }

    float* C = Cout + (size_t)ks * 256 * N;
#pragma unroll
    for (int i = 0; i < 4; i++)
#pragma unroll
        for (int j = 0; j < 2; j++)
            wmma::store_matrix_sync(
                C + (size_t)(wm * 64 + i * 16) * N + n0 + wn * 32 + j * 16,
                acc[i][j], N, wmma::mem_row_major);
}

// ---------------------------------------------------------------------------
// Gate kernel (scalar, one thread per gate element — 512 blocks):
// reduce KS split-K partials + bias, LSTM nonlinearity (i,f,g,o; relu).
// Optionally writes hdup (half [h|h]), hflat_h (half), out_tail (f32 h4).
// ---------------------------------------------------------------------------
__global__ void lstm_gate(const float* __restrict__ P, int KS,
                          const float* __restrict__ c_prev, float* __restrict__ c_out,
                          const float* __restrict__ bias,
                          __half* __restrict__ hdup, __half* __restrict__ hflat_h,
                          float* __restrict__ out_tail) {
    int idx = blockIdx.x * blockDim.x + threadIdx.x;
    if (idx >= Bn * Hn) return;
    int b = idx / Hn;
    int j = idx - b * Hn;
    float zi = bias[j], zf = bias[Hn + j], zg = bias[2 * Hn + j], zo = bias[3 * Hn + j];
    for (int ks = 0; ks < KS; ks++) {
        const float* zr = P + ((size_t)ks * Bn + b) * NG;
        zi += zr[j]; zf += zr[Hn + j]; zg += zr[2 * Hn + j]; zo += zr[3 * Hn + j];
    }
    float ig = 1.f / (1.f + expf(-zi));
    float fg = 1.f / (1.f + expf(-zf));
    float gg = fmaxf(zg, 0.f);
    float og = 1.f / (1.f + expf(-zo));
    float cn = fg * c_prev[idx] + ig * gg;
    c_out[idx] = cn;
    float h = og * fmaxf(cn, 0.f);
    if (hdup) {
        __half hh = __float2half_rn(h);
        hdup[(size_t)b * 2 * Hn + j] = hh;
        hdup[(size_t)b * 2 * Hn + Hn + j] = hh;
    }
    if (hflat_h) hflat_h[idx] = __float2half_rn(h);
    if (out_tail) out_tail[idx] = h;
}

// ---------------------------------------------------------------------------
// SMEM-staged softmax on (Bn x Vn): one global read + one global write.
// ---------------------------------------------------------------------------
__global__ __launch_bounds__(512)
void softmax_smem(float* __restrict__ probs, const float* __restrict__ bd) {
    extern __shared__ float sx[];
    const int b = blockIdx.x;
    float* row = probs + (size_t)b * Vn;
    const int tid = threadIdx.x;
    const int nt = 512;
    __shared__ float sred[33];

    float m = -3.4e38f;
    for (int i = tid; i < Vn; i += nt) {
        float v = row[i] + bd[i];
        sx[i] = v;
        m = fmaxf(m, v);
    }
#pragma unroll
    for (int o = 16; o > 0; o >>= 1) m = fmaxf(m, __shfl_xor_sync(0xffffffffu, m, o));
    if ((tid & 31) == 0) sred[tid >> 5] = m;
    __syncthreads();
    if (tid == 0) {
        float v = sred[0];
        for (int w = 1; w < nt / 32; w++) v = fmaxf(v, sred[w]);
        sred[32] = v;
    }
    __syncthreads();
    m = sred[32];

    float s = 0.f;
    for (int i = tid; i < Vn; i += nt) {
        float e = expf(sx[i] - m);
        sx[i] = e;
        s += e;
    }
    __syncthreads();
#pragma unroll
    for (int o = 16; o > 0; o >>= 1) s += __shfl_xor_sync(0xffffffffu, s, o);
    if ((tid & 31) == 0) sred[tid >> 5] = s;
    __syncthreads();
    if (tid == 0) {
        float v = 0.f;
        for (int w = 0; w < nt / 32; w++) v += sred[w];
        sred[32] = v;
    }
    __syncthreads();
    float inv = 1.f / sred[32];

    for (int i = tid; i < Vn; i += nt) row[i] = sx[i] * inv;
}

// ---------------------------------------------------------------------------
// Launch
// ---------------------------------------------------------------------------
extern "C" void kernel_launch(void* const* d_in, const int* in_sizes, int n_in,
                              void* d_out, int out_size) {
    const float* enc = (const float*)d_in[0];
    const float* we  = (const float*)d_in[1];
    const float* h0  = (const float*)d_in[2];
    const float* c0  = (const float*)d_in[3];
    const int*   spk = (const int*)d_in[4];
    // d_in[5] = addressee (unused)
    const float* pe  = (const float*)d_in[6];
    const float* W1 = (const float*)d_in[7];
    const float* U1 = (const float*)d_in[8];
    const float* b1 = (const float*)d_in[9];
    const float* W2 = (const float*)d_in[10];
    const float* U2 = (const float*)d_in[11];
    const float* b2 = (const float*)d_in[12];
    const float* W3 = (const float*)d_in[13];
    const float* U3 = (const float*)d_in[14];
    const float* b3 = (const float*)d_in[15];
    const float* W4 = (const float*)d_in[16];
    const float* U4 = (const float*)d_in[17];
    const float* b4 = (const float*)d_in[18];
    const float* Wd = (const float*)d_in[19];
    const float* bd = (const float*)d_in[20];
    float* out = (float*)d_out;

    __half *xh, *hdh, *h4h;
    float *pp, *cp;
    cudaGetSymbolAddress((void**)&xh, g_xh);
    cudaGetSymbolAddress((void**)&hdh, g_hduph);
    cudaGetSymbolAddress((void**)&h4h, g_h4h);
    cudaGetSymbolAddress((void**)&pp, g_part);
    cudaGetSymbolAddress((void**)&cp, g_c);

    const bool tail = (out_size >= Bn * Vn + 2 * Bn * Hn);
    float* tail_h = tail ? out + (size_t)Bn * Vn : nullptr;
    float* tail_c = tail ? out + (size_t)Bn * Vn + Bn * Hn : cp;

    cudaFuncSetAttribute(gemm_cp<0>, cudaFuncAttributeMaxDynamicSharedMemorySize,
                         GEMM_SMEM);
    cudaFuncSetAttribute(gemm_cp<1>, cudaFuncAttributeMaxDynamicSharedMemorySize,
                         GEMM_SMEM);
    cudaFuncSetAttribute(softmax_smem, cudaFuncAttributeMaxDynamicSharedMemorySize,
                         Vn * (int)sizeof(float));

    const int GATE_GRID = (Bn * Hn + 255) / 256;   // 512 blocks

    // 1. Build concatenated input (half)
    build_x<<<(Bn * K1 + 255) / 256, 256>>>(enc, we, h0, spk, pe);

    // 2. Layer 1: z = [x|h0] @ [W1;U1]  (K=11776, split 11264, KS=8)
    gemm_cp<1><<<dim3(NG / 64, 1, 8), 256, GEMM_SMEM>>>(
        xh, W1, U1, pp, NG, K1, DIN1, K1 / 8);
    lstm_gate<<<GATE_GRID, 256>>>(pp, 8, c0, cp, b1, hdh, nullptr, nullptr);

    // 3. Layers 2-4: z = [h|h] @ [W;U]  (K=1024, split 512, KS=8, iters=4)
    gemm_cp<1><<<dim3(NG / 64, 1, 8), 256, GEMM_SMEM>>>(
        hdh, W2, U2, pp, NG, 2 * Hn, Hn, 2 * Hn / 8);
    lstm_gate<<<GATE_GRID, 256>>>(pp, 8, cp, cp, b2, hdh, nullptr, nullptr);

    gemm_cp<1><<<dim3(NG / 64, 1, 8), 256, GEMM_SMEM>>>(
        hdh, W3, U3, pp, NG, 2 * Hn, Hn, 2 * Hn / 8);
    lstm_gate<<<GATE_GRID, 256>>>(pp, 8, cp, cp, b3, hdh, nullptr, nullptr);

    gemm_cp<1><<<dim3(NG / 64, 1, 8), 256, GEMM_SMEM>>>(
        hdh, W4, U4, pp, NG, 2 * Hn, Hn, 2 * Hn / 8);
    // Final gate: h4 (half) for decode + h4/c4 straight into the output tail
    lstm_gate<<<GATE_GRID, 256>>>(pp, 8, cp, tail_c, b4, nullptr, h4h, tail_h);

    // 4. Decode: logits = h4 @ Wd (KS=1, direct into out), softmax in place
    gemm_cp<0><<<dim3(Vn / 64, 1, 1), 256, GEMM_SMEM>>>(
        h4h, Wd, nullptr, out, Vn, Hn, 0, Hn);
    softmax_smem<<<Bn, 512, Vn * sizeof(float)>>>(out, bd);
}

// round 15
// speedup vs baseline: 1.0898x; 1.0898x over previous
#include <cuda_runtime.h>
#include <cuda_fp16.h>
#include <mma.h>
#include <math.h>
#include <cstdint>

using namespace nvcuda;

// Problem dims
static constexpr int Bn = 256, Sn = 20, En = 512, Hn = 512, Vn = 32000;
static constexpr int DIN1 = Sn * En + 2 * En;   // 11264
static constexpr int K1   = DIN1 + Hn;          // 11776 ([x | h0] concat)
static constexpr int NG   = 4 * Hn;             // 2048 gates

// Scratch (device globals; allocation is forbidden)
__device__ __align__(16) __half g_xh[Bn * K1];        // A of layer 1 (half)
__device__ __align__(16) __half g_hduph[Bn * 2 * Hn]; // [h|h] half (layers 2-4 A)
__device__ __align__(16) __half g_h4h[Bn * Hn];       // h4 half (decode A)
__device__ float g_part[8 * Bn * NG];                 // split-K partials
__device__ float g_c[Bn * Hn];

// ---------------------------------------------------------------------------
// Helpers
// ---------------------------------------------------------------------------
#define CP16(dst, src) \
    asm volatile("cp.async.cg.shared.global [%0], [%1], 16;\n" :: "r"(dst), "l"(src))

__device__ __forceinline__ void split4h(const float4 f, __half* hi, __half* lo) {
    float v[4] = {f.x, f.y, f.z, f.w};
#pragma unroll
    for (int i = 0; i < 4; i++) {
        __half h = __float2half_rn(v[i]);
        hi[i] = h;
        lo[i] = __float2half_rn(v[i] - __half2float(h));
    }
}
__device__ __forceinline__ void cvt4h(const float4 f, __half* o) {
    o[0] = __float2half_rn(f.x);
    o[1] = __float2half_rn(f.y);
    o[2] = __float2half_rn(f.z);
    o[3] = __float2half_rn(f.w);
}

// ---------------------------------------------------------------------------
// build_x: concatenated input row as HALF: [enc | we | pe[spk] | h0]
// ---------------------------------------------------------------------------
__global__ void build_x(const float* __restrict__ enc, const float* __restrict__ we,
                        const float* __restrict__ h0, const int* __restrict__ spk,
                        const float* __restrict__ pe) {
    int idx = blockIdx.x * blockDim.x + threadIdx.x;
    if (idx >= Bn * K1) return;
    int b = idx / K1;
    int k = idx - b * K1;
    float v;
    if (k < Sn * En)            v = enc[b * Sn * En + k];
    else if (k < Sn * En + En)  v = we[b * En + (k - Sn * En)];
    else if (k < DIN1)          v = pe[spk[b] * En + (k - Sn * En - En)];
    else                        v = h0[b * Hn + (k - DIN1)];
    g_xh[idx] = __float2half_rn(v);
}

// ---------------------------------------------------------------------------
// Deep-pipelined fp16 GEMM (tall 256x64, BK=32, 3-stage cp.async) — the
// PROVEN R13 loop.
//   A: half in gmem -> cp.async direct.   B: f32 -> stage -> half plane(s).
//   SPLIT=1: B = bh + bl (2-MMA compensation).  SPLIT=0: B = bh only (1 MMA;
//   for the decode GEMM where post-softmax sensitivity to fp16 weight
//   rounding is ~1e-4).
// grid = (N/64, 1, KS). 256 threads, 8 warps (4x2), warp tile 64x32.
// ---------------------------------------------------------------------------
static constexpr int ALD = 40;                  // halfs per A row (32+8 pad)
static constexpr int BLD = 72;                  // halfs per B half-plane row
static constexpr int BFLD = 68;                 // floats per B f32 stage row
static constexpr int A_STAGE = 256 * ALD * 2;   // 20480 B
static constexpr int BF_STAGE = 32 * BFLD * 4;  // 8704 B
static constexpr int BH_STAGE = 32 * BLD * 2;   // 4608 B
static constexpr int SA  = 0;                   // 3 stages
static constexpr int SBF = SA + 3 * A_STAGE;    // 3 stages
static constexpr int SBH = SBF + 3 * BF_STAGE;  // 2 buffers
static constexpr int SBL = SBH + 2 * BH_STAGE;  // 2 buffers
static constexpr int GEMM_SMEM = SBL + 2 * BH_STAGE;  // 105984 B

template <int DUAL, int SPLIT>
__global__ __launch_bounds__(256, 2)
void gemm_cp(const __half* __restrict__ A, const float* __restrict__ B0,
             const float* __restrict__ B1, float* __restrict__ Cout,
             int N, int K, int Ksplit, int Kchunk) {
    extern __shared__ char smem[];
    uint32_t sb;
    asm("{ .reg .u64 t; cvta.to.shared.u64 t, %1; cvt.u32.u64 %0, t; }"
        : "=r"(sb) : "l"(smem));

    const int n0 = blockIdx.x * 64;
    const int ks = blockIdx.z;
    const int kbase = ks * Kchunk;
    const int iters = Kchunk / 32;
    const int tid = threadIdx.x;

    // A loader: 4 threads per row (4x16B = 64B row), 4 passes of 64 rows
    const int a_row4 = tid >> 2;
    const int a_chk = tid & 3;
    // B loader: 16 threads per row (16x16B = 256B row), 2 passes of 16 rows
    const int b_row16 = tid >> 4;
    const int b_chk = tid & 15;
    // B converter: 8 threads per row (8 floats each)
    const int c_row = tid >> 3;
    const int c_col = (tid & 7) * 8;

    const int wid = tid >> 5;
    const int wm = wid >> 1;   // 0..3 -> m offset wm*64
    const int wn = wid & 1;    // 0..1 -> n offset wn*32

    wmma::fragment<wmma::accumulator, 16, 16, 16, float> acc[4][2];
#pragma unroll
    for (int i = 0; i < 4; i++)
#pragma unroll
        for (int j = 0; j < 2; j++) wmma::fill_fragment(acc[i][j], 0.f);

    auto issue_chunk = [&](int chunk) {
        const int s = chunk % 3;
        const int k0 = kbase + chunk * 32;
        uint32_t sa = sb + SA + s * A_STAGE;
#pragma unroll
        for (int p = 0; p < 4; p++) {
            int row = a_row4 + p * 64;
            const __half* src = A + (size_t)row * K + k0 + a_chk * 8;
            CP16(sa + row * 80 + a_chk * 16, src);
        }
        uint32_t sf = sb + SBF + s * BF_STAGE;
#pragma unroll
        for (int p = 0; p < 2; p++) {
            int gk = k0 + b_row16 + p * 16;
            const float* src;
            if (DUAL && gk >= Ksplit)
                src = B1 + (size_t)(gk - Ksplit) * N + n0 + b_chk * 4;
            else
                src = B0 + (size_t)gk * N + n0 + b_chk * 4;
            CP16(sf + (b_row16 + p * 16) * 272 + b_chk * 16, src);
        }
        asm volatile("cp.async.commit_group;\n");
    };

    issue_chunk(0);
    if (iters > 1) issue_chunk(1);

    for (int it = 0; it < iters; ++it) {
        const int s = it % 3;
        const int sd = it & 1;

        if (it == iters - 1)
            asm volatile("cp.async.wait_group 0;\n");
        else
            asm volatile("cp.async.wait_group 1;\n");
        __syncthreads();   // chunk `it` visible; all warps done with chunk it-1

        if (it + 2 < iters) issue_chunk(it + 2);

        // Convert B f32 stage -> half plane(s) (double-buffered)
        {
            const float* bf = (const float*)(smem + SBF + s * BF_STAGE);
            float4 f0 = *(const float4*)(bf + c_row * BFLD + c_col);
            float4 f1 = *(const float4*)(bf + c_row * BFLD + c_col + 4);
            __half* bh = (__half*)(smem + SBH + sd * BH_STAGE);
            if (SPLIT) {
                __half h0[4], l0[4], h1[4], l1[4];
                split4h(f0, h0, l0);
                split4h(f1, h1, l1);
                __half* bl = (__half*)(smem + SBL + sd * BH_STAGE);
                *(uint2*)&bh[c_row * BLD + c_col] = *(uint2*)h0;
                *(uint2*)&bh[c_row * BLD + c_col + 4] = *(uint2*)h1;
                *(uint2*)&bl[c_row * BLD + c_col] = *(uint2*)l0;
                *(uint2*)&bl[c_row * BLD + c_col + 4] = *(uint2*)l1;
            } else {
                __half h0[4], h1[4];
                cvt4h(f0, h0);
                cvt4h(f1, h1);
                *(uint2*)&bh[c_row * BLD + c_col] = *(uint2*)h0;
                *(uint2*)&bh[c_row * BLD + c_col + 4] = *(uint2*)h1;
            }
        }
        __syncthreads();

        const __half* ah = (const __half*)(smem + SA + s * A_STAGE) + (wm * 64) * ALD;
        const __half* bh = (const __half*)(smem + SBH + sd * BH_STAGE) + wn * 32;
        const __half* bl = (const __half*)(smem + SBL + sd * BH_STAGE) + wn * 32;

#pragma unroll
        for (int kk = 0; kk < 2; ++kk) {
            wmma::fragment<wmma::matrix_a, 16, 16, 16, __half, wmma::row_major> af[4];
            wmma::fragment<wmma::matrix_b, 16, 16, 16, __half, wmma::row_major> bfh[2],
                bfl[2];
#pragma unroll
            for (int i = 0; i < 4; i++)
                wmma::load_matrix_sync(af[i], ah + i * 16 * ALD + kk * 16, ALD);
#pragma unroll
            for (int j = 0; j < 2; j++) {
                wmma::load_matrix_sync(bfh[j], bh + kk * 16 * BLD + j * 16, BLD);
                if (SPLIT)
                    wmma::load_matrix_sync(bfl[j], bl + kk * 16 * BLD + j * 16, BLD);
            }
#pragma unroll
            for (int i = 0; i < 4; i++)
#pragma unroll
                for (int j = 0; j < 2; j++) {
                    wmma::mma_sync(acc[i][j], af[i], bfh[j], acc[i][j]);
                    if (SPLIT)
                        wmma::mma_sync(acc[i][j], af[i], bfl[j], acc[i][j]);
                }
        }
    }

    float* C = Cout + (size_t)ks * 256 * N;
#pragma unroll
    for (int i = 0; i < 4; i++)
#pragma unroll
        for (int j = 0; j < 2; j++)
            wmma::store_matrix_sync(
                C + (size_t)(wm * 64 + i * 16) * N + n0 + wn * 32 + j * 16,
                acc[i][j], N, wmma::mem_row_major);
}

// ---------------------------------------------------------------------------
// Gate kernel (scalar, one thread per gate element — 512 blocks):
// reduce KS split-K partials + bias, LSTM nonlinearity (i,f,g,o; relu).
// Optionally writes hdup (half [h|h]), hflat_h (half), out_tail (f32 h4).
// ---------------------------------------------------------------------------
__global__ void lstm_gate(const float* __restrict__ P, int KS,
                          const float* __restrict__ c_prev, float* __restrict__ c_out,
                          const float* __restrict__ bias,
                          __half* __restrict__ hdup, __half* __restrict__ hflat_h,
                          float* __restrict__ out_tail) {
    int idx = blockIdx.x * blockDim.x + threadIdx.x;
    if (idx >= Bn * Hn) return;
    int b = idx / Hn;
    int j = idx - b * Hn;
    float zi = bias[j], zf = bias[Hn + j], zg = bias[2 * Hn + j], zo = bias[3 * Hn + j];
    for (int ks = 0; ks < KS; ks++) {
        const float* zr = P + ((size_t)ks * Bn + b) * NG;
        zi += zr[j]; zf += zr[Hn + j]; zg += zr[2 * Hn + j]; zo += zr[3 * Hn + j];
    }
    float ig = 1.f / (1.f + expf(-zi));
    float fg = 1.f / (1.f + expf(-zf));
    float gg = fmaxf(zg, 0.f);
    float og = 1.f / (1.f + expf(-zo));
    float cn = fg * c_prev[idx] + ig * gg;
    c_out[idx] = cn;
    float h = og * fmaxf(cn, 0.f);
    if (hdup) {
        __half hh = __float2half_rn(h);
        hdup[(size_t)b * 2 * Hn + j] = hh;
        hdup[(size_t)b * 2 * Hn + Hn + j] = hh;
    }
    if (hflat_h) hflat_h[idx] = __float2half_rn(h);
    if (out_tail) out_tail[idx] = h;
}

// ---------------------------------------------------------------------------
// SMEM-staged softmax on (Bn x Vn): one global read + one global write.
// ---------------------------------------------------------------------------
__global__ __launch_bounds__(512)
void softmax_smem(float* __restrict__ probs, const float* __restrict__ bd) {
    extern __shared__ float sx[];
    const int b = blockIdx.x;
    float* row = probs + (size_t)b * Vn;
    const int tid = threadIdx.x;
    const int nt = 512;
    __shared__ float sred[33];

    float m = -3.4e38f;
    for (int i = tid; i < Vn; i += nt) {
        float v = row[i] + bd[i];
        sx[i] = v;
        m = fmaxf(m, v);
    }
#pragma unroll
    for (int o = 16; o > 0; o >>= 1) m = fmaxf(m, __shfl_xor_sync(0xffffffffu, m, o));
    if ((tid & 31) == 0) sred[tid >> 5] = m;
    __syncthreads();
    if (tid == 0) {
        float v = sred[0];
        for (int w = 1; w < nt / 32; w++) v = fmaxf(v, sred[w]);
        sred[32] = v;
    }
    __syncthreads();
    m = sred[32];

    float s = 0.f;
    for (int i = tid; i < Vn; i += nt) {
        float e = expf(sx[i] - m);
        sx[i] = e;
        s += e;
    }
    __syncthreads();
#pragma unroll
    for (int o = 16; o > 0; o >>= 1) s += __shfl_xor_sync(0xffffffffu, s, o);
    if ((tid & 31) == 0) sred[tid >> 5] = s;
    __syncthreads();
    if (tid == 0) {
        float v = 0.f;
        for (int w = 0; w < nt / 32; w++) v += sred[w];
        sred[32] = v;
    }
    __syncthreads();
    float inv = 1.f / sred[32];

    for (int i = tid; i < Vn; i += nt) row[i] = sx[i] * inv;
}

// ---------------------------------------------------------------------------
// Launch
// ---------------------------------------------------------------------------
extern "C" void kernel_launch(void* const* d_in, const int* in_sizes, int n_in,
                              void* d_out, int out_size) {
    const float* enc = (const float*)d_in[0];
    const float* we  = (const float*)d_in[1];
    const float* h0  = (const float*)d_in[2];
    const float* c0  = (const float*)d_in[3];
    const int*   spk = (const int*)d_in[4];
    // d_in[5] = addressee (unused)
    const float* pe  = (const float*)d_in[6];
    const float* W1 = (const float*)d_in[7];
    const float* U1 = (const float*)d_in[8];
    const float* b1 = (const float*)d_in[9];
    const float* W2 = (const float*)d_in[10];
    const float* U2 = (const float*)d_in[11];
    const float* b2 = (const float*)d_in[12];
    const float* W3 = (const float*)d_in[13];
    const float* U3 = (const float*)d_in[14];
    const float* b3 = (const float*)d_in[15];
    const float* W4 = (const float*)d_in[16];
    const float* U4 = (const float*)d_in[17];
    const float* b4 = (const float*)d_in[18];
    const float* Wd = (const float*)d_in[19];
    const float* bd = (const float*)d_in[20];
    float* out = (float*)d_out;

    __half *xh, *hdh, *h4h;
    float *pp, *cp;
    cudaGetSymbolAddress((void**)&xh, g_xh);
    cudaGetSymbolAddress((void**)&hdh, g_hduph);
    cudaGetSymbolAddress((void**)&h4h, g_h4h);
    cudaGetSymbolAddress((void**)&pp, g_part);
    cudaGetSymbolAddress((void**)&cp, g_c);

    const bool tail = (out_size >= Bn * Vn + 2 * Bn * Hn);
    float* tail_h = tail ? out + (size_t)Bn * Vn : nullptr;
    float* tail_c = tail ? out + (size_t)Bn * Vn + Bn * Hn : cp;

    cudaFuncSetAttribute((const void*)gemm_cp<0, 0>,
                         cudaFuncAttributeMaxDynamicSharedMemorySize, GEMM_SMEM);
    cudaFuncSetAttribute((const void*)gemm_cp<1, 1>,
                         cudaFuncAttributeMaxDynamicSharedMemorySize, GEMM_SMEM);
    cudaFuncSetAttribute((const void*)softmax_smem,
                         cudaFuncAttributeMaxDynamicSharedMemorySize,
                         Vn * (int)sizeof(float));

    const int GATE_GRID = (Bn * Hn + 255) / 256;   // 512 blocks

    // 1. Build concatenated input (half)
    build_x<<<(Bn * K1 + 255) / 256, 256>>>(enc, we, h0, spk, pe);

    // 2. Layer 1: z = [x|h0] @ [W1;U1]  (K=11776, split 11264, KS=8, 2-plane)
    gemm_cp<1, 1><<<dim3(NG / 64, 1, 8), 256, GEMM_SMEM>>>(
        xh, W1, U1, pp, NG, K1, DIN1, K1 / 8);
    lstm_gate<<<GATE_GRID, 256>>>(pp, 8, c0, cp, b1, hdh, nullptr, nullptr);

    // 3. Layers 2-4: z = [h|h] @ [W;U]  (K=1024, split 512, KS=8, 2-plane)
    gemm_cp<1, 1><<<dim3(NG / 64, 1, 8), 256, GEMM_SMEM>>>(
        hdh, W2, U2, pp, NG, 2 * Hn, Hn, 2 * Hn / 8);
    lstm_gate<<<GATE_GRID, 256>>>(pp, 8, cp, cp, b2, hdh, nullptr, nullptr);

    gemm_cp<1, 1><<<dim3(NG / 64, 1, 8), 256, GEMM_SMEM>>>(
        hdh, W3, U3, pp, NG, 2 * Hn, Hn, 2 * Hn / 8);
    lstm_gate<<<GATE_GRID, 256>>>(pp, 8, cp, cp, b3, hdh, nullptr, nullptr);

    gemm_cp<1, 1><<<dim3(NG / 64, 1, 8), 256, GEMM_SMEM>>>(
        hdh, W4, U4, pp, NG, 2 * Hn, Hn, 2 * Hn / 8);
    lstm_gate<<<GATE_GRID, 256>>>(pp, 8, cp, tail_c, b4, nullptr, h4h, tail_h);

    // 4. Decode: logits = h4 @ Wd — SINGLE fp16 plane (post-softmax weight
    //    rounding sensitivity ~1e-4). KS=1, direct into out.
    gemm_cp<0, 0><<<dim3(Vn / 64, 1, 1), 256, GEMM_SMEM>>>(
        h4h, Wd, nullptr, out, Vn, Hn, 0, Hn);
    softmax_smem<<<Bn, 512, Vn * sizeof(float)>>>(out, bd);
}

// round 16
// speedup vs baseline: 1.1913x; 1.0932x over previous
#include <cuda_runtime.h>
#include <cuda_fp16.h>
#include <mma.h>
#include <math.h>
#include <cstdint>

using namespace nvcuda;

// Problem dims
static constexpr int Bn = 256, Sn = 20, En = 512, Hn = 512, Vn = 32000;
static constexpr int DIN1 = Sn * En + 2 * En;   // 11264
static constexpr int K1   = DIN1 + Hn;          // 11776 ([x | h0] concat)
static constexpr int NG   = 4 * Hn;             // 2048 gates

// Scratch (device globals; allocation is forbidden)
__device__ __align__(16) __half g_xh[Bn * K1];        // A of layer 1 (half)
__device__ __align__(16) __half g_hduph[Bn * 2 * Hn]; // [h|h] half (layers 2-4 A)
__device__ __align__(16) __half g_h4h[Bn * Hn];       // h4 half (decode A)
__device__ float g_part[8 * Bn * NG];                 // split-K partials
__device__ float g_c[Bn * Hn];

// ---------------------------------------------------------------------------
// Helpers
// ---------------------------------------------------------------------------
#define CP16(dst, src) \
    asm volatile("cp.async.cg.shared.global [%0], [%1], 16;\n" :: "r"(dst), "l"(src))

__device__ __forceinline__ void split4h(const float4 f, __half* hi, __half* lo) {
    float v[4] = {f.x, f.y, f.z, f.w};
#pragma unroll
    for (int i = 0; i < 4; i++) {
        __half h = __float2half_rn(v[i]);
        hi[i] = h;
        lo[i] = __float2half_rn(v[i] - __half2float(h));
    }
}
__device__ __forceinline__ void cvt4h(const float4 f, __half* o) {
    o[0] = __float2half_rn(f.x);
    o[1] = __float2half_rn(f.y);
    o[2] = __float2half_rn(f.z);
    o[3] = __float2half_rn(f.w);
}

// ---------------------------------------------------------------------------
// build_x: concatenated input row as HALF: [enc | we | pe[spk] | h0]
// ---------------------------------------------------------------------------
__global__ void build_x(const float* __restrict__ enc, const float* __restrict__ we,
                        const float* __restrict__ h0, const int* __restrict__ spk,
                        const float* __restrict__ pe) {
    int idx = blockIdx.x * blockDim.x + threadIdx.x;
    if (idx >= Bn * K1) return;
    int b = idx / K1;
    int k = idx - b * K1;
    float v;
    if (k < Sn * En)            v = enc[b * Sn * En + k];
    else if (k < Sn * En + En)  v = we[b * En + (k - Sn * En)];
    else if (k < DIN1)          v = pe[spk[b] * En + (k - Sn * En - En)];
    else                        v = h0[b * Hn + (k - DIN1)];
    g_xh[idx] = __float2half_rn(v);
}

// ---------------------------------------------------------------------------
// Deep-pipelined fp16 GEMM (tall 256x64, BK=32, 3-stage cp.async) — the
// PROVEN R13 loop.
//   A: half in gmem -> cp.async direct.   B: f32 -> stage -> half plane(s).
//   SPLIT=1: B = bh + bl (2-MMA compensation) — recurrent layers (error
//   compounds through 3 further sigmoid layers).
//   SPLIT=0: B = bh only — layer 1 and decode (adds weight-rounding noise of
//   the same order as the existing activation noise: ~sqrt(2) x rel_err).
// grid = (N/64, 1, KS). 256 threads, 8 warps (4x2), warp tile 64x32.
// ---------------------------------------------------------------------------
static constexpr int ALD = 40;                  // halfs per A row (32+8 pad)
static constexpr int BLD = 72;                  // halfs per B half-plane row
static constexpr int BFLD = 68;                 // floats per B f32 stage row
static constexpr int A_STAGE = 256 * ALD * 2;   // 20480 B
static constexpr int BF_STAGE = 32 * BFLD * 4;  // 8704 B
static constexpr int BH_STAGE = 32 * BLD * 2;   // 4608 B
static constexpr int SA  = 0;                   // 3 stages
static constexpr int SBF = SA + 3 * A_STAGE;    // 3 stages
static constexpr int SBH = SBF + 3 * BF_STAGE;  // 2 buffers
static constexpr int SBL = SBH + 2 * BH_STAGE;  // 2 buffers
static constexpr int GEMM_SMEM = SBL + 2 * BH_STAGE;  // 105984 B

template <int DUAL, int SPLIT>
__global__ __launch_bounds__(256, 2)
void gemm_cp(const __half* __restrict__ A, const float* __restrict__ B0,
             const float* __restrict__ B1, float* __restrict__ Cout,
             int N, int K, int Ksplit, int Kchunk) {
    extern __shared__ char smem[];
    uint32_t sb;
    asm("{ .reg .u64 t; cvta.to.shared.u64 t, %1; cvt.u32.u64 %0, t; }"
        : "=r"(sb) : "l"(smem));

    const int n0 = blockIdx.x * 64;
    const int ks = blockIdx.z;
    const int kbase = ks * Kchunk;
    const int iters = Kchunk / 32;
    const int tid = threadIdx.x;

    // A loader: 4 threads per row (4x16B = 64B row), 4 passes of 64 rows
    const int a_row4 = tid >> 2;
    const int a_chk = tid & 3;
    // B loader: 16 threads per row (16x16B = 256B row), 2 passes of 16 rows
    const int b_row16 = tid >> 4;
    const int b_chk = tid & 15;
    // B converter: 8 threads per row (8 floats each)
    const int c_row = tid >> 3;
    const int c_col = (tid & 7) * 8;

    const int wid = tid >> 5;
    const int wm = wid >> 1;   // 0..3 -> m offset wm*64
    const int wn = wid & 1;    // 0..1 -> n offset wn*32

    wmma::fragment<wmma::accumulator, 16, 16, 16, float> acc[4][2];
#pragma unroll
    for (int i = 0; i < 4; i++)
#pragma unroll
        for (int j = 0; j < 2; j++) wmma::fill_fragment(acc[i][j], 0.f);

    auto issue_chunk = [&](int chunk) {
        const int s = chunk % 3;
        const int k0 = kbase + chunk * 32;
        uint32_t sa = sb + SA + s * A_STAGE;
#pragma unroll
        for (int p = 0; p < 4; p++) {
            int row = a_row4 + p * 64;
            const __half* src = A + (size_t)row * K + k0 + a_chk * 8;
            CP16(sa + row * 80 + a_chk * 16, src);
        }
        uint32_t sf = sb + SBF + s * BF_STAGE;
#pragma unroll
        for (int p = 0; p < 2; p++) {
            int gk = k0 + b_row16 + p * 16;
            const float* src;
            if (DUAL && gk >= Ksplit)
                src = B1 + (size_t)(gk - Ksplit) * N + n0 + b_chk * 4;
            else
                src = B0 + (size_t)gk * N + n0 + b_chk * 4;
            CP16(sf + (b_row16 + p * 16) * 272 + b_chk * 16, src);
        }
        asm volatile("cp.async.commit_group;\n");
    };

    issue_chunk(0);
    if (iters > 1) issue_chunk(1);

    for (int it = 0; it < iters; ++it) {
        const int s = it % 3;
        const int sd = it & 1;

        if (it == iters - 1)
            asm volatile("cp.async.wait_group 0;\n");
        else
            asm volatile("cp.async.wait_group 1;\n");
        __syncthreads();   // chunk `it` visible; all warps done with chunk it-1

        if (it + 2 < iters) issue_chunk(it + 2);

        // Convert B f32 stage -> half plane(s) (double-buffered)
        {
            const float* bf = (const float*)(smem + SBF + s * BF_STAGE);
            float4 f0 = *(const float4*)(bf + c_row * BFLD + c_col);
            float4 f1 = *(const float4*)(bf + c_row * BFLD + c_col + 4);
            __half* bh = (__half*)(smem + SBH + sd * BH_STAGE);
            if (SPLIT) {
                __half h0[4], l0[4], h1[4], l1[4];
                split4h(f0, h0, l0);
                split4h(f1, h1, l1);
                __half* bl = (__half*)(smem + SBL + sd * BH_STAGE);
                *(uint2*)&bh[c_row * BLD + c_col] = *(uint2*)h0;
                *(uint2*)&bh[c_row * BLD + c_col + 4] = *(uint2*)h1;
                *(uint2*)&bl[c_row * BLD + c_col] = *(uint2*)l0;
                *(uint2*)&bl[c_row * BLD + c_col + 4] = *(uint2*)l1;
            } else {
                __half h0[4], h1[4];
                cvt4h(f0, h0);
                cvt4h(f1, h1);
                *(uint2*)&bh[c_row * BLD + c_col] = *(uint2*)h0;
                *(uint2*)&bh[c_row * BLD + c_col + 4] = *(uint2*)h1;
            }
        }
        __syncthreads();

        const __half* ah = (const __half*)(smem + SA + s * A_STAGE) + (wm * 64) * ALD;
        const __half* bh = (const __half*)(smem + SBH + sd * BH_STAGE) + wn * 32;
        const __half* bl = (const __half*)(smem + SBL + sd * BH_STAGE) + wn * 32;

#pragma unroll
        for (int kk = 0; kk < 2; ++kk) {
            wmma::fragment<wmma::matrix_a, 16, 16, 16, __half, wmma::row_major> af[4];
            wmma::fragment<wmma::matrix_b, 16, 16, 16, __half, wmma::row_major> bfh[2],
                bfl[2];
#pragma unroll
            for (int i = 0; i < 4; i++)
                wmma::load_matrix_sync(af[i], ah + i * 16 * ALD + kk * 16, ALD);
#pragma unroll
            for (int j = 0; j < 2; j++) {
                wmma::load_matrix_sync(bfh[j], bh + kk * 16 * BLD + j * 16, BLD);
                if (SPLIT)
                    wmma::load_matrix_sync(bfl[j], bl + kk * 16 * BLD + j * 16, BLD);
            }
#pragma unroll
            for (int i = 0; i < 4; i++)
#pragma unroll
                for (int j = 0; j < 2; j++) {
                    wmma::mma_sync(acc[i][j], af[i], bfh[j], acc[i][j]);
                    if (SPLIT)
                        wmma::mma_sync(acc[i][j], af[i], bfl[j], acc[i][j]);
                }
        }
    }

    float* C = Cout + (size_t)ks * 256 * N;
#pragma unroll
    for (int i = 0; i < 4; i++)
#pragma unroll
        for (int j = 0; j < 2; j++)
            wmma::store_matrix_sync(
                C + (size_t)(wm * 64 + i * 16) * N + n0 + wn * 32 + j * 16,
                acc[i][j], N, wmma::mem_row_major);
}

// ---------------------------------------------------------------------------
// Gate kernel (scalar, one thread per gate element — 512 blocks):
// reduce KS split-K partials + bias, LSTM nonlinearity (i,f,g,o; relu).
// Optionally writes hdup (half [h|h]), hflat_h (half), out_tail (f32 h4).
// ---------------------------------------------------------------------------
__global__ void lstm_gate(const float* __restrict__ P, int KS,
                          const float* __restrict__ c_prev, float* __restrict__ c_out,
                          const float* __restrict__ bias,
                          __half* __restrict__ hdup, __half* __restrict__ hflat_h,
                          float* __restrict__ out_tail) {
    int idx = blockIdx.x * blockDim.x + threadIdx.x;
    if (idx >= Bn * Hn) return;
    int b = idx / Hn;
    int j = idx - b * Hn;
    float zi = bias[j], zf = bias[Hn + j], zg = bias[2 * Hn + j], zo = bias[3 * Hn + j];
    for (int ks = 0; ks < KS; ks++) {
        const float* zr = P + ((size_t)ks * Bn + b) * NG;
        zi += zr[j]; zf += zr[Hn + j]; zg += zr[2 * Hn + j]; zo += zr[3 * Hn + j];
    }
    float ig = 1.f / (1.f + expf(-zi));
    float fg = 1.f / (1.f + expf(-zf));
    float gg = fmaxf(zg, 0.f);
    float og = 1.f / (1.f + expf(-zo));
    float cn = fg * c_prev[idx] + ig * gg;
    c_out[idx] = cn;
    float h = og * fmaxf(cn, 0.f);
    if (hdup) {
        __half hh = __float2half_rn(h);
        hdup[(size_t)b * 2 * Hn + j] = hh;
        hdup[(size_t)b * 2 * Hn + Hn + j] = hh;
    }
    if (hflat_h) hflat_h[idx] = __float2half_rn(h);
    if (out_tail) out_tail[idx] = h;
}

// ---------------------------------------------------------------------------
// SMEM-staged softmax on (Bn x Vn), 1024 threads (smem caps at 1 block/SM
// regardless; more threads = more loads in flight on this latency-bound pass).
// ---------------------------------------------------------------------------
__global__ __launch_bounds__(1024)
void softmax_smem(float* __restrict__ probs, const float* __restrict__ bd) {
    extern __shared__ float sx[];
    const int b = blockIdx.x;
    float* row = probs + (size_t)b * Vn;
    const int tid = threadIdx.x;
    const int nt = 1024;
    __shared__ float sred[33];

    float m = -3.4e38f;
    for (int i = tid; i < Vn; i += nt) {
        float v = row[i] + bd[i];
        sx[i] = v;
        m = fmaxf(m, v);
    }
#pragma unroll
    for (int o = 16; o > 0; o >>= 1) m = fmaxf(m, __shfl_xor_sync(0xffffffffu, m, o));
    if ((tid & 31) == 0) sred[tid >> 5] = m;
    __syncthreads();
    if (tid == 0) {
        float v = sred[0];
        for (int w = 1; w < nt / 32; w++) v = fmaxf(v, sred[w]);
        sred[32] = v;
    }
    __syncthreads();
    m = sred[32];

    float s = 0.f;
    for (int i = tid; i < Vn; i += nt) {
        float e = expf(sx[i] - m);
        sx[i] = e;
        s += e;
    }
    __syncthreads();
#pragma unroll
    for (int o = 16; o > 0; o >>= 1) s += __shfl_xor_sync(0xffffffffu, s, o);
    if ((tid & 31) == 0) sred[tid >> 5] = s;
    __syncthreads();
    if (tid == 0) {
        float v = 0.f;
        for (int w = 0; w < nt / 32; w++) v += sred[w];
        sred[32] = v;
    }
    __syncthreads();
    float inv = 1.f / sred[32];

    for (int i = tid; i < Vn; i += nt) row[i] = sx[i] * inv;
}

// ---------------------------------------------------------------------------
// Launch
// ---------------------------------------------------------------------------
extern "C" void kernel_launch(void* const* d_in, const int* in_sizes, int n_in,
                              void* d_out, int out_size) {
    const float* enc = (const float*)d_in[0];
    const float* we  = (const float*)d_in[1];
    const float* h0  = (const float*)d_in[2];
    const float* c0  = (const float*)d_in[3];
    const int*   spk = (const int*)d_in[4];
    // d_in[5] = addressee (unused)
    const float* pe  = (const float*)d_in[6];
    const float* W1 = (const float*)d_in[7];
    const float* U1 = (const float*)d_in[8];
    const float* b1 = (const float*)d_in[9];
    const float* W2 = (const float*)d_in[10];
    const float* U2 = (const float*)d_in[11];
    const float* b2 = (const float*)d_in[12];
    const float* W3 = (const float*)d_in[13];
    const float* U3 = (const float*)d_in[14];
    const float* b3 = (const float*)d_in[15];
    const float* W4 = (const float*)d_in[16];
    const float* U4 = (const float*)d_in[17];
    const float* b4 = (const float*)d_in[18];
    const float* Wd = (const float*)d_in[19];
    const float* bd = (const float*)d_in[20];
    float* out = (float*)d_out;

    __half *xh, *hdh, *h4h;
    float *pp, *cp;
    cudaGetSymbolAddress((void**)&xh, g_xh);
    cudaGetSymbolAddress((void**)&hdh, g_hduph);
    cudaGetSymbolAddress((void**)&h4h, g_h4h);
    cudaGetSymbolAddress((void**)&pp, g_part);
    cudaGetSymbolAddress((void**)&cp, g_c);

    const bool tail = (out_size >= Bn * Vn + 2 * Bn * Hn);
    float* tail_h = tail ? out + (size_t)Bn * Vn : nullptr;
    float* tail_c = tail ? out + (size_t)Bn * Vn + Bn * Hn : cp;

    cudaFuncSetAttribute((const void*)gemm_cp<0, 0>,
                         cudaFuncAttributeMaxDynamicSharedMemorySize, GEMM_SMEM);
    cudaFuncSetAttribute((const void*)gemm_cp<1, 0>,
                         cudaFuncAttributeMaxDynamicSharedMemorySize, GEMM_SMEM);
    cudaFuncSetAttribute((const void*)gemm_cp<1, 1>,
                         cudaFuncAttributeMaxDynamicSharedMemorySize, GEMM_SMEM);
    cudaFuncSetAttribute((const void*)softmax_smem,
                         cudaFuncAttributeMaxDynamicSharedMemorySize,
                         Vn * (int)sizeof(float));

    const int GATE_GRID = (Bn * Hn + 255) / 256;   // 512 blocks

    // 1. Build concatenated input (half)
    build_x<<<(Bn * K1 + 255) / 256, 256>>>(enc, we, h0, spk, pe);

    // 2. Layer 1: z = [x|h0] @ [W1;U1] — SINGLE fp16 plane (weight noise is
    //    same order as existing activation noise: ~sqrt(2) x rel_err total).
    gemm_cp<1, 0><<<dim3(NG / 64, 1, 8), 256, GEMM_SMEM>>>(
        xh, W1, U1, pp, NG, K1, DIN1, K1 / 8);
    lstm_gate<<<GATE_GRID, 256>>>(pp, 8, c0, cp, b1, hdh, nullptr, nullptr);

    // 3. Layers 2-4: z = [h|h] @ [W;U]  (K=1024, split 512, KS=8, 2-plane)
    gemm_cp<1, 1><<<dim3(NG / 64, 1, 8), 256, GEMM_SMEM>>>(
        hdh, W2, U2, pp, NG, 2 * Hn, Hn, 2 * Hn / 8);
    lstm_gate<<<GATE_GRID, 256>>>(pp, 8, cp, cp, b2, hdh, nullptr, nullptr);

    gemm_cp<1, 1><<<dim3(NG / 64, 1, 8), 256, GEMM_SMEM>>>(
        hdh, W3, U3, pp, NG, 2 * Hn, Hn, 2 * Hn / 8);
    lstm_gate<<<GATE_GRID, 256>>>(pp, 8, cp, cp, b3, hdh, nullptr, nullptr);

    gemm_cp<1, 1><<<dim3(NG / 64, 1, 8), 256, GEMM_SMEM>>>(
        hdh, W4, U4, pp, NG, 2 * Hn, Hn, 2 * Hn / 8);
    lstm_gate<<<GATE_GRID, 256>>>(pp, 8, cp, tail_c, b4, nullptr, h4h, tail_h);

    // 4. Decode: logits = h4 @ Wd — SINGLE fp16 plane. KS=1, direct into out.
    gemm_cp<0, 0><<<dim3(Vn / 64, 1, 1), 256, GEMM_SMEM>>>(
        h4h, Wd, nullptr, out, Vn, Hn, 0, Hn);
    softmax_smem<<<Bn, 1024, Vn * sizeof(float)>>>(out, bd);
}